// round 1
// baseline (speedup 1.0000x reference)
#include <cuda_runtime.h>

#define BATCH 8
#define CCH   512
#define HW    64
#define PIX   (HW*HW)              // 4096
#define TOT   (BATCH*CCH*PIX)      // 16,777,216 elements per tensor

// Scratch (allocation-free rule: __device__ globals)
__device__ float g_f_opt[TOT];
__device__ float g_f_sar[TOT];
__device__ float g_S_opt[TOT];
__device__ float g_S_sar[TOT];

// ---------------- packed f32x2 helpers ----------------
__device__ __forceinline__ unsigned long long pack_dup(float a) {
    unsigned long long d;
    unsigned int ai = __float_as_uint(a);
    asm("mov.b64 %0, {%1, %1};" : "=l"(d) : "r"(ai));
    return d;
}
__device__ __forceinline__ void ffma2(unsigned long long& d,
                                      unsigned long long a,
                                      unsigned long long b) {
    asm("fma.rn.f32x2 %0, %1, %2, %0;" : "+l"(d) : "l"(a), "l"(b));
}
__device__ __forceinline__ float2 u2f(unsigned long long v) {
    float2 r;
    asm("mov.b64 {%0, %1}, %2;" : "=f"(r.x), "=f"(r.y) : "l"(v));
    return r;
}

// ---------------- Kernel 1: 1x1 conv = batched GEMM ----------------
// F[b][o][p] = sum_c W[o][c] * X[b][c][p]
// Tile: 128(o) x 128(p) x 16(c), 256 threads, 8x8 per thread via f32x2.
__global__ __launch_bounds__(256, 2)
void conv_gemm(const float* __restrict__ X, const float* __restrict__ W, int which) {
    __shared__ float As[16][132];   // A transposed: As[k][m], padded
    __shared__ float Bs[16][128];

    float* F = which ? g_f_sar : g_f_opt;

    const int b  = blockIdx.z;
    const int m0 = blockIdx.y * 128;
    const int p0 = blockIdx.x * 128;
    const int tid = threadIdx.x;
    const int tm = tid >> 4;        // 0..15
    const int tn = tid & 15;        // 0..15

    const float* Xb = X + (size_t)b * CCH * PIX;
    float* Fb       = F + (size_t)b * CCH * PIX;

    unsigned long long acc[8][4];
#pragma unroll
    for (int i = 0; i < 8; i++)
#pragma unroll
        for (int j = 0; j < 4; j++) acc[i][j] = 0ull;

    for (int k0 = 0; k0 < CCH; k0 += 16) {
        // Load A tile (128 x 16): slot s -> m = s>>2, k4 = (s&3)*4
#pragma unroll
        for (int r = 0; r < 2; r++) {
            int s  = tid + r * 256;
            int m  = s >> 2;
            int k4 = (s & 3) * 4;
            float4 v = *(const float4*)(W + (size_t)(m0 + m) * CCH + k0 + k4);
            As[k4 + 0][m] = v.x; As[k4 + 1][m] = v.y;
            As[k4 + 2][m] = v.z; As[k4 + 3][m] = v.w;
        }
        // Load B tile (16 x 128): slot s -> k = s>>5, p4 = (s&31)*4
#pragma unroll
        for (int r = 0; r < 2; r++) {
            int s  = tid + r * 256;
            int k  = s >> 5;
            int p4 = (s & 31) * 4;
            *(float4*)&Bs[k][p4] =
                *(const float4*)(Xb + (size_t)(k0 + k) * PIX + p0 + p4);
        }
        __syncthreads();

#pragma unroll
        for (int kk = 0; kk < 16; kk++) {
            float4 a0 = *(const float4*)&As[kk][tm * 8];
            float4 a1 = *(const float4*)&As[kk][tm * 8 + 4];
            ulonglong2 b0 = *(const ulonglong2*)&Bs[kk][tn * 8];
            ulonglong2 b1 = *(const ulonglong2*)&Bs[kk][tn * 8 + 4];
            unsigned long long bp0 = b0.x, bp1 = b0.y, bp2 = b1.x, bp3 = b1.y;
            float av[8] = {a0.x, a0.y, a0.z, a0.w, a1.x, a1.y, a1.z, a1.w};
#pragma unroll
            for (int i = 0; i < 8; i++) {
                unsigned long long ad = pack_dup(av[i]);
                ffma2(acc[i][0], ad, bp0);
                ffma2(acc[i][1], ad, bp1);
                ffma2(acc[i][2], ad, bp2);
                ffma2(acc[i][3], ad, bp3);
            }
        }
        __syncthreads();
    }

    // Write back 8 rows x 8 cols
#pragma unroll
    for (int i = 0; i < 8; i++) {
        float* dst = Fb + (size_t)(m0 + tm * 8 + i) * PIX + p0 + tn * 8;
        float2 l0 = u2f(acc[i][0]), l1 = u2f(acc[i][1]);
        float2 l2 = u2f(acc[i][2]), l3 = u2f(acc[i][3]);
        *(float4*)(dst)     = make_float4(l0.x, l0.y, l1.x, l1.y);
        *(float4*)(dst + 4) = make_float4(l2.x, l2.y, l3.x, l3.y);
    }
}

// ---------------- Kernel 2: Gram matrices ----------------
// S[bc][i][j] = sum_h F[bc][h][i] * F[bc][h][j], 64x64x64 per block
__global__ __launch_bounds__(256)
void gram(int which) {
    __shared__ float T[64 * 64];

    const float* F = which ? g_f_sar : g_f_opt;
    float*       S = which ? g_S_sar : g_S_opt;

    const int bc  = blockIdx.x;           // b*CCH + c
    const int tid = threadIdx.x;
    const float* src = F + (size_t)bc * PIX;

#pragma unroll
    for (int r = 0; r < 4; r++) {
        int s = tid + r * 256;
        *(float4*)&T[s * 4] = *(const float4*)(src + s * 4);
    }
    __syncthreads();

    const int tx = tid & 15, ty = tid >> 4;
    const int i0 = ty * 4, j0 = tx * 4;

    unsigned long long acc[4][2];
#pragma unroll
    for (int i = 0; i < 4; i++) { acc[i][0] = 0ull; acc[i][1] = 0ull; }

#pragma unroll 4
    for (int h = 0; h < 64; h++) {
        float4 a = *(const float4*)&T[h * 64 + i0];
        ulonglong2 bv = *(const ulonglong2*)&T[h * 64 + j0];
        float av[4] = {a.x, a.y, a.z, a.w};
#pragma unroll
        for (int i = 0; i < 4; i++) {
            unsigned long long ad = pack_dup(av[i]);
            ffma2(acc[i][0], ad, bv.x);
            ffma2(acc[i][1], ad, bv.y);
        }
    }

    float* dst = S + (size_t)bc * PIX;
#pragma unroll
    for (int i = 0; i < 4; i++) {
        float2 l0 = u2f(acc[i][0]), l1 = u2f(acc[i][1]);
        *(float4*)(dst + (i0 + i) * 64 + j0) = make_float4(l0.x, l0.y, l1.x, l1.y);
    }
}

// ---------------- Kernel 3: channel softmax (axis=1) + combine ----------------
// out[b,c,p] = f_o * f_s * had^2, had = softmax_c(S_o) * softmax_c(S_s)
__global__ __launch_bounds__(128)
void smax_combine(float* __restrict__ out) {
    const int q = blockIdx.x * blockDim.x + threadIdx.x;   // [0, BATCH*PIX)
    const int b = q >> 12;
    const int p = q & (PIX - 1);

    const size_t base = (size_t)b * CCH * PIX + p;
    const float* so = g_S_opt + base;
    const float* ss = g_S_sar + base;

    float mo = -3.0e38f, sumo = 0.f;
    float ms = -3.0e38f, sums = 0.f;

#pragma unroll 8
    for (int c = 0; c < CCH; c++) {
        float v = so[(size_t)c * PIX];
        float w = ss[(size_t)c * PIX];
        float mo2 = fmaxf(mo, v);
        sumo = sumo * __expf(mo - mo2) + __expf(v - mo2);
        mo = mo2;
        float ms2 = fmaxf(ms, w);
        sums = sums * __expf(ms - ms2) + __expf(w - ms2);
        ms = ms2;
    }
    const float io = 1.0f / sumo;
    const float is = 1.0f / sums;

    const float* fo = g_f_opt + base;
    const float* fs = g_f_sar + base;
    float* o = out + base;

#pragma unroll 8
    for (int c = 0; c < CCH; c++) {
        size_t off = (size_t)c * PIX;
        float had = (__expf(so[off] - mo) * io) * (__expf(ss[off] - ms) * is);
        o[off] = fo[off] * fs[off] * had * had;
    }
}

// ---------------- launch ----------------
extern "C" void kernel_launch(void* const* d_in, const int* in_sizes, int n_in,
                              void* d_out, int out_size) {
    const float* opt = (const float*)d_in[0];
    const float* sar = (const float*)d_in[1];
    const float* Wo  = (const float*)d_in[2];
    const float* Ws  = (const float*)d_in[3];
    float* out = (float*)d_out;

    dim3 g1(PIX / 128, CCH / 128, BATCH);     // (32, 4, 8)
    conv_gemm<<<g1, 256>>>(opt, Wo, 0);
    conv_gemm<<<g1, 256>>>(sar, Ws, 1);

    gram<<<BATCH * CCH, 256>>>(0);
    gram<<<BATCH * CCH, 256>>>(1);

    smax_combine<<<(BATCH * PIX) / 128, 128>>>(out);
}

// round 3
// speedup vs baseline: 1.1155x; 1.1155x over previous
#include <cuda_runtime.h>
#include <cuda_bf16.h>
#include <cstdint>

#define BATCH 8
#define CCH   512
#define PIX   4096
#define TOT   (BATCH*CCH*PIX)      // 16,777,216

// ---------------- scratch (__device__ globals; no alloc allowed) ----------------
__device__ float g_f_opt[TOT];
__device__ float g_f_sar[TOT];
__device__ float g_S_opt[TOT];
__device__ float g_S_sar[TOT];

// bf16 3-way splits of X, TRANSPOSED to [b][p][c]  (K contiguous for B operand)
__device__ __nv_bfloat16 g_x0[2][TOT];
__device__ __nv_bfloat16 g_x1[2][TOT];
__device__ __nv_bfloat16 g_x2[2][TOT];
// bf16 3-way splits of W, [o][c] (K contiguous for A operand)
__device__ __nv_bfloat16 g_w0[2][CCH*CCH];
__device__ __nv_bfloat16 g_w1[2][CCH*CCH];
__device__ __nv_bfloat16 g_w2[2][CCH*CCH];

// ---------------- helpers ----------------
__device__ __forceinline__ uint32_t smem_u32(const void* p) {
    uint32_t a;
    asm("{ .reg .u64 t; cvta.to.shared.u64 t, %1; cvt.u32.u64 %0, t; }" : "=r"(a) : "l"(p));
    return a;
}
__device__ __forceinline__ void cp16(uint32_t dst, const void* src) {
    asm volatile("cp.async.cg.shared.global [%0], [%1], 16;" :: "r"(dst), "l"(src));
}
#define CP_COMMIT() asm volatile("cp.async.commit_group;" ::: "memory")
#define CP_WAIT(n)  asm volatile("cp.async.wait_group %0;" :: "n"(n) : "memory")

__device__ __forceinline__ void ldsm4(uint32_t& r0, uint32_t& r1, uint32_t& r2, uint32_t& r3,
                                      uint32_t addr) {
    asm volatile("ldmatrix.sync.aligned.m8n8.x4.shared.b16 {%0,%1,%2,%3}, [%4];"
                 : "=r"(r0), "=r"(r1), "=r"(r2), "=r"(r3) : "r"(addr));
}
__device__ __forceinline__ void mma16816(float* c, const uint32_t* a, const uint32_t* b) {
    asm volatile("mma.sync.aligned.m16n8k16.row.col.f32.bf16.bf16.f32 "
                 "{%0,%1,%2,%3}, {%4,%5,%6,%7}, {%8,%9}, {%0,%1,%2,%3};"
                 : "+f"(c[0]), "+f"(c[1]), "+f"(c[2]), "+f"(c[3])
                 : "r"(a[0]), "r"(a[1]), "r"(a[2]), "r"(a[3]), "r"(b[0]), "r"(b[1]));
}

// packed f32x2 (gram kernel)
__device__ __forceinline__ unsigned long long pack_dup(float a) {
    unsigned long long d; unsigned int ai = __float_as_uint(a);
    asm("mov.b64 %0, {%1, %1};" : "=l"(d) : "r"(ai));
    return d;
}
__device__ __forceinline__ void ffma2(unsigned long long& d, unsigned long long a, unsigned long long b) {
    asm("fma.rn.f32x2 %0, %1, %2, %0;" : "+l"(d) : "l"(a), "l"(b));
}
__device__ __forceinline__ float2 u2f(unsigned long long v) {
    float2 r; asm("mov.b64 {%0, %1}, %2;" : "=f"(r.x), "=f"(r.y) : "l"(v));
    return r;
}

// ---------------- Kernel A: split + transpose X ----------------
__global__ __launch_bounds__(256)
void split_x(const float* __restrict__ x, int which) {
    __shared__ float tile[64 * 68];
    const int b = blockIdx.z, c0 = blockIdx.y * 64, p0 = blockIdx.x * 64;
    const int tid = threadIdx.x;

    const float* src = x + ((size_t)(b * CCH + c0)) * PIX + p0;
    const int cl = tid >> 4, pl4 = (tid & 15) * 4;
#pragma unroll
    for (int it = 0; it < 4; it++) {
        float4 v = *(const float4*)(src + (size_t)(cl + it * 16) * PIX + pl4);
        *(float4*)&tile[(cl + it * 16) * 68 + pl4] = v;
    }
    __syncthreads();

    const int pl = tid >> 2, q = (tid & 3) * 16;
    __nv_bfloat16 o0[16], o1[16], o2[16];
#pragma unroll
    for (int j = 0; j < 16; j++) {
        float a = tile[(q + j) * 68 + pl];
        __nv_bfloat16 h = __float2bfloat16(a);
        float r = a - __bfloat162float(h);
        __nv_bfloat16 m = __float2bfloat16(r);
        float r2 = r - __bfloat162float(m);
        o0[j] = h; o1[j] = m; o2[j] = __float2bfloat16(r2);
    }
    size_t off = ((size_t)(b * PIX + p0 + pl)) * CCH + c0 + q;
    ((uint4*)&g_x0[which][off])[0] = ((uint4*)o0)[0];
    ((uint4*)&g_x0[which][off])[1] = ((uint4*)o0)[1];
    ((uint4*)&g_x1[which][off])[0] = ((uint4*)o1)[0];
    ((uint4*)&g_x1[which][off])[1] = ((uint4*)o1)[1];
    ((uint4*)&g_x2[which][off])[0] = ((uint4*)o2)[0];
    ((uint4*)&g_x2[which][off])[1] = ((uint4*)o2)[1];
}

// ---------------- Kernel B: split W ----------------
__global__ __launch_bounds__(256)
void split_w(const float* __restrict__ w, int which) {
    int i = (blockIdx.x * 256 + threadIdx.x) * 4;
    float4 v = *(const float4*)(w + i);
    float av[4] = {v.x, v.y, v.z, v.w};
    __nv_bfloat16 o0[4], o1[4], o2[4];
#pragma unroll
    for (int j = 0; j < 4; j++) {
        __nv_bfloat16 h = __float2bfloat16(av[j]);
        float r = av[j] - __bfloat162float(h);
        __nv_bfloat16 m = __float2bfloat16(r);
        float r2 = r - __bfloat162float(m);
        o0[j] = h; o1[j] = m; o2[j] = __float2bfloat16(r2);
    }
    *(uint2*)&g_w0[which][i] = *(uint2*)o0;
    *(uint2*)&g_w1[which][i] = *(uint2*)o1;
    *(uint2*)&g_w2[which][i] = *(uint2*)o2;
}

// ---------------- Kernel C: conv via mma.sync (legacy HMMA), 3-split bf16 ----------------
// F[b][o][p] = sum_c W[o][c] X[b][c][p]; block 128x128, K-chunk 32, double-buffered cp.async
#define BK     32
#define PITCH  40                       // bf16 per smem row (pad: conflict-free ldmatrix)
#define TILE_E (128 * PITCH)            // 5120 bf16 per split tile
#define BUF_E  (6 * TILE_E)             // A(3) + B(3) per buffer
#define NCHUNK (CCH / BK)               // 16

__global__ __launch_bounds__(256, 1)
void conv_mma(int which) {
    extern __shared__ __nv_bfloat16 sm[];

    const int tid = threadIdx.x;
    const int lane = tid & 31, warp = tid >> 5;
    const int wm = warp >> 2, wn = warp & 3;         // 2 x 4 warp grid, tile 64(m) x 32(n)
    const int b = blockIdx.z, m0 = blockIdx.y * 128, p0 = blockIdx.x * 128;

    const __nv_bfloat16* xs[3] = {g_x0[which], g_x1[which], g_x2[which]};
    const __nv_bfloat16* ws[3] = {g_w0[which], g_w1[which], g_w2[which]};
    float* F = which ? g_f_sar : g_f_opt;

    const uint32_t smA = smem_u32(sm);               // buffer 0 base (bytes)

    float acc[4][4][4];
#pragma unroll
    for (int i = 0; i < 4; i++)
#pragma unroll
        for (int j = 0; j < 4; j++)
#pragma unroll
            for (int k = 0; k < 4; k++) acc[i][j][k] = 0.f;

    // ---- async tile loader: 1536 cp.async x 16B per side ----
    auto load_chunk = [&](int c) {
        const int kc = c * BK;
        const int bi = c & 1;
        const uint32_t dstA = smA + bi * (BUF_E * 2);
        const uint32_t dstB = dstA + 3 * TILE_E * 2;
#pragma unroll
        for (int r = 0; r < 6; r++) {
            int i = tid + r * 256;                   // [0,1536)
            int s = i >> 9, rem = i & 511, row = rem >> 2, seg = rem & 3;
            cp16(dstA + (s * TILE_E + row * PITCH + seg * 8) * 2,
                 ws[s] + (size_t)(m0 + row) * CCH + kc + seg * 8);
        }
#pragma unroll
        for (int r = 0; r < 6; r++) {
            int i = tid + r * 256;
            int s = i >> 9, rem = i & 511, row = rem >> 2, seg = rem & 3;
            cp16(dstB + (s * TILE_E + row * PITCH + seg * 8) * 2,
                 xs[s] + ((size_t)(b * PIX + p0 + row)) * CCH + kc + seg * 8);
        }
        CP_COMMIT();
    };

    load_chunk(0);

    const int sa_idx[6] = {0, 0, 1, 1, 0, 2};
    const int sb_idx[6] = {0, 1, 0, 1, 2, 0};

    for (int c = 0; c < NCHUNK; c++) {
        if (c + 1 < NCHUNK) { load_chunk(c + 1); CP_WAIT(1); }
        else                { CP_WAIT(0); }
        __syncthreads();

        const int bi = c & 1;
        const uint32_t bA = smA + bi * (BUF_E * 2);
        const uint32_t bB = bA + 3 * TILE_E * 2;

#pragma unroll
        for (int ks = 0; ks < 2; ks++) {
            uint32_t Af[3][4][4], Bf[3][4][2];
            // A fragments: rows m, cols k  (row-major m16k16 via ldmatrix.x4)
#pragma unroll
            for (int s = 0; s < 3; s++)
#pragma unroll
                for (int mi = 0; mi < 4; mi++) {
                    int row = wm * 64 + mi * 16 + (lane & 15);
                    int col = ks * 16 + ((lane >> 4) << 3);
                    ldsm4(Af[s][mi][0], Af[s][mi][1], Af[s][mi][2], Af[s][mi][3],
                          bA + (s * TILE_E + row * PITCH + col) * 2);
                }
            // B fragments: col-major k16n8 (Bs is [n][k], k contiguous) via ldmatrix.x4
#pragma unroll
            for (int s = 0; s < 3; s++)
#pragma unroll
                for (int ni = 0; ni < 2; ni++) {
                    int row = wn * 32 + ni * 16 + ((lane >> 4) << 3) + (lane & 7);
                    int col = ks * 16 + (((lane >> 3) & 1) << 3);
                    uint32_t r0, r1, r2, r3;
                    ldsm4(r0, r1, r2, r3, bB + (s * TILE_E + row * PITCH + col) * 2);
                    Bf[s][2 * ni][0] = r0; Bf[s][2 * ni][1] = r1;
                    Bf[s][2 * ni + 1][0] = r2; Bf[s][2 * ni + 1][1] = r3;
                }
            // 6 split-product passes
#pragma unroll
            for (int pr = 0; pr < 6; pr++) {
                const int sa = sa_idx[pr], sb = sb_idx[pr];
#pragma unroll
                for (int mi = 0; mi < 4; mi++)
#pragma unroll
                    for (int nf = 0; nf < 4; nf++)
                        mma16816(acc[mi][nf], Af[sa][mi], Bf[sb][nf]);
            }
        }
        __syncthreads();
    }

    // ---- writeback: C frag (m16n8): c0,c1 -> (m=lane>>2, n=(lane&3)*2); c2,c3 -> m+8
#pragma unroll
    for (int mi = 0; mi < 4; mi++) {
#pragma unroll
        for (int nf = 0; nf < 4; nf++) {
            int m = m0 + wm * 64 + mi * 16 + (lane >> 2);
            int n = p0 + wn * 32 + nf * 8 + (lane & 3) * 2;
            float* d0 = F + ((size_t)(b * CCH + m)) * PIX + n;
            *(float2*)d0 = make_float2(acc[mi][nf][0], acc[mi][nf][1]);
            *(float2*)(d0 + 8 * PIX) = make_float2(acc[mi][nf][2], acc[mi][nf][3]);
        }
    }
}

// ---------------- Kernel D: Gram matrices ----------------
__global__ __launch_bounds__(256)
void gram(int which) {
    __shared__ float T[64 * 64];
    const float* F = which ? g_f_sar : g_f_opt;
    float*       S = which ? g_S_sar : g_S_opt;
    const int bc = blockIdx.x;
    const int tid = threadIdx.x;
    const float* src = F + (size_t)bc * PIX;

#pragma unroll
    for (int r = 0; r < 4; r++) {
        int s = tid + r * 256;
        *(float4*)&T[s * 4] = *(const float4*)(src + s * 4);
    }
    __syncthreads();

    const int tx = tid & 15, ty = tid >> 4;
    const int i0 = ty * 4, j0 = tx * 4;
    unsigned long long acc[4][2];
#pragma unroll
    for (int i = 0; i < 4; i++) { acc[i][0] = 0ull; acc[i][1] = 0ull; }

#pragma unroll 4
    for (int h = 0; h < 64; h++) {
        float4 a = *(const float4*)&T[h * 64 + i0];
        ulonglong2 bv = *(const ulonglong2*)&T[h * 64 + j0];
        float av[4] = {a.x, a.y, a.z, a.w};
#pragma unroll
        for (int i = 0; i < 4; i++) {
            unsigned long long ad = pack_dup(av[i]);
            ffma2(acc[i][0], ad, bv.x);
            ffma2(acc[i][1], ad, bv.y);
        }
    }
    float* dst = S + (size_t)bc * PIX;
#pragma unroll
    for (int i = 0; i < 4; i++) {
        float2 l0 = u2f(acc[i][0]), l1 = u2f(acc[i][1]);
        *(float4*)(dst + (i0 + i) * 64 + j0) = make_float4(l0.x, l0.y, l1.x, l1.y);
    }
}

// ---------------- Kernel E: channel softmax + combine ----------------
__global__ __launch_bounds__(128)
void smax_combine(float* __restrict__ out) {
    const int q = blockIdx.x * blockDim.x + threadIdx.x;
    const int b = q >> 12;
    const int p = q & (PIX - 1);
    const size_t bs = (size_t)b * CCH * PIX + p;
    const float* so = g_S_opt + bs;
    const float* ss = g_S_sar + bs;

    float mo = -3.0e38f, sumo = 0.f, ms = -3.0e38f, sums = 0.f;
#pragma unroll 8
    for (int c = 0; c < CCH; c++) {
        float v = so[(size_t)c * PIX];
        float w = ss[(size_t)c * PIX];
        float mo2 = fmaxf(mo, v);
        sumo = sumo * __expf(mo - mo2) + __expf(v - mo2); mo = mo2;
        float ms2 = fmaxf(ms, w);
        sums = sums * __expf(ms - ms2) + __expf(w - ms2); ms = ms2;
    }
    const float io = 1.0f / sumo, is = 1.0f / sums;
    const float* fo = g_f_opt + bs;
    const float* fs = g_f_sar + bs;
    float* o = out + bs;
#pragma unroll 8
    for (int c = 0; c < CCH; c++) {
        size_t off = (size_t)c * PIX;
        float had = (__expf(so[off] - mo) * io) * (__expf(ss[off] - ms) * is);
        o[off] = fo[off] * fs[off] * had * had;
    }
}

// ---------------- launch ----------------
extern "C" void kernel_launch(void* const* d_in, const int* in_sizes, int n_in,
                              void* d_out, int out_size) {
    const float* opt = (const float*)d_in[0];
    const float* sar = (const float*)d_in[1];
    const float* Wo  = (const float*)d_in[2];
    const float* Ws  = (const float*)d_in[3];
    float* out = (float*)d_out;

    static const int SMEM_CONV = 2 * BUF_E * 2;      // 122880 B
    cudaFuncSetAttribute(conv_mma, cudaFuncAttributeMaxDynamicSharedMemorySize, SMEM_CONV);

    dim3 gs(64, 8, BATCH);
    split_x<<<gs, 256>>>(opt, 0);
    split_x<<<gs, 256>>>(sar, 1);
    split_w<<<CCH * CCH / 1024, 256>>>(Wo, 0);
    split_w<<<CCH * CCH / 1024, 256>>>(Ws, 1);

    dim3 gc(PIX / 128, CCH / 128, BATCH);            // (32, 4, 8)
    conv_mma<<<gc, 256, SMEM_CONV>>>(0);
    conv_mma<<<gc, 256, SMEM_CONV>>>(1);

    gram<<<BATCH * CCH, 256>>>(0);
    gram<<<BATCH * CCH, 256>>>(1);

    smax_combine<<<(BATCH * PIX) / 128, 128>>>(out);
}

// round 4
// speedup vs baseline: 1.6179x; 1.4504x over previous
#include <cuda_runtime.h>
#include <cuda_fp16.h>
#include <cstdint>

#define BATCH 8
#define CCH   512
#define PIX   4096
#define TOT   (BATCH*CCH*PIX)      // 16,777,216

// ---------------- scratch (__device__ globals; no alloc allowed) ----------------
__device__ float g_f_opt[TOT];
__device__ float g_f_sar[TOT];
__device__ float g_S_opt[TOT];
__device__ float g_S_sar[TOT];

// fp16 2-way splits of X, TRANSPOSED to [b][p][c]  (K contiguous for B operand)
__device__ __half g_x0[2][TOT];
__device__ __half g_x1[2][TOT];
// fp16 2-way splits of W, [o][c] (K contiguous for A operand)
__device__ __half g_w0[2][CCH*CCH];
__device__ __half g_w1[2][CCH*CCH];

// ---------------- helpers ----------------
__device__ __forceinline__ uint32_t smem_u32(const void* p) {
    uint32_t a;
    asm("{ .reg .u64 t; cvta.to.shared.u64 t, %1; cvt.u32.u64 %0, t; }" : "=r"(a) : "l"(p));
    return a;
}
__device__ __forceinline__ void cp16(uint32_t dst, const void* src) {
    asm volatile("cp.async.cg.shared.global [%0], [%1], 16;" :: "r"(dst), "l"(src));
}
#define CP_COMMIT() asm volatile("cp.async.commit_group;" ::: "memory")
#define CP_WAIT(n)  asm volatile("cp.async.wait_group %0;" :: "n"(n) : "memory")

__device__ __forceinline__ void ldsm4(uint32_t& r0, uint32_t& r1, uint32_t& r2, uint32_t& r3,
                                      uint32_t addr) {
    asm volatile("ldmatrix.sync.aligned.m8n8.x4.shared.b16 {%0,%1,%2,%3}, [%4];"
                 : "=r"(r0), "=r"(r1), "=r"(r2), "=r"(r3) : "r"(addr));
}
__device__ __forceinline__ void mma16816(float* c, const uint32_t* a, const uint32_t* b) {
    asm volatile("mma.sync.aligned.m16n8k16.row.col.f32.f16.f16.f32 "
                 "{%0,%1,%2,%3}, {%4,%5,%6,%7}, {%8,%9}, {%0,%1,%2,%3};"
                 : "+f"(c[0]), "+f"(c[1]), "+f"(c[2]), "+f"(c[3])
                 : "r"(a[0]), "r"(a[1]), "r"(a[2]), "r"(a[3]), "r"(b[0]), "r"(b[1]));
}

// packed f32x2 (gram kernel)
__device__ __forceinline__ unsigned long long pack_dup(float a) {
    unsigned long long d; unsigned int ai = __float_as_uint(a);
    asm("mov.b64 %0, {%1, %1};" : "=l"(d) : "r"(ai));
    return d;
}
__device__ __forceinline__ void ffma2(unsigned long long& d, unsigned long long a, unsigned long long b) {
    asm("fma.rn.f32x2 %0, %1, %2, %0;" : "+l"(d) : "l"(a), "l"(b));
}
__device__ __forceinline__ float2 u2f(unsigned long long v) {
    float2 r; asm("mov.b64 {%0, %1}, %2;" : "=f"(r.x), "=f"(r.y) : "l"(v));
    return r;
}

// ---------------- Kernel A: split + transpose X (both inputs, fp16 2-split) ----------------
// grid.z in [0,16): which = z>>3, b = z&7
__global__ __launch_bounds__(256)
void split_x(const float* __restrict__ opt, const float* __restrict__ sar) {
    __shared__ float tile[64 * 68];
    const int which = blockIdx.z >> 3, b = blockIdx.z & 7;
    const int c0 = blockIdx.y * 64, p0 = blockIdx.x * 64;
    const int tid = threadIdx.x;
    const float* x = which ? sar : opt;

    const float* src = x + ((size_t)(b * CCH + c0)) * PIX + p0;
    const int cl = tid >> 4, pl4 = (tid & 15) * 4;
#pragma unroll
    for (int it = 0; it < 4; it++) {
        float4 v = *(const float4*)(src + (size_t)(cl + it * 16) * PIX + pl4);
        *(float4*)&tile[(cl + it * 16) * 68 + pl4] = v;
    }
    __syncthreads();

    const int pl = tid >> 2, q = (tid & 3) * 16;
    __half o0[16], o1[16];
#pragma unroll
    for (int j = 0; j < 16; j++) {
        float a = tile[(q + j) * 68 + pl];
        __half h = __float2half_rn(a);
        o0[j] = h;
        o1[j] = __float2half_rn(a - __half2float(h));
    }
    size_t off = ((size_t)(b * PIX + p0 + pl)) * CCH + c0 + q;
    ((uint4*)&g_x0[which][off])[0] = ((uint4*)o0)[0];
    ((uint4*)&g_x0[which][off])[1] = ((uint4*)o0)[1];
    ((uint4*)&g_x1[which][off])[0] = ((uint4*)o1)[0];
    ((uint4*)&g_x1[which][off])[1] = ((uint4*)o1)[1];
}

// ---------------- Kernel B: split W (both) ----------------
__global__ __launch_bounds__(256)
void split_w(const float* __restrict__ Wo, const float* __restrict__ Ws) {
    const int which = blockIdx.y;
    const float* w = which ? Ws : Wo;
    int i = (blockIdx.x * 256 + threadIdx.x) * 4;
    float4 v = *(const float4*)(w + i);
    float av[4] = {v.x, v.y, v.z, v.w};
    __half o0[4], o1[4];
#pragma unroll
    for (int j = 0; j < 4; j++) {
        __half h = __float2half_rn(av[j]);
        o0[j] = h;
        o1[j] = __float2half_rn(av[j] - __half2float(h));
    }
    *(uint2*)&g_w0[which][i] = *(uint2*)o0;
    *(uint2*)&g_w1[which][i] = *(uint2*)o1;
}

// ---------------- Kernel C: conv via mma.sync, fp16 2-split, 3 passes ----------------
// F[b][o][p] = sum_c W[o][c] X[b][c][p]; block 128x128, K-chunk 64, double-buffered cp.async
#define BK     64
#define PITCH  72                       // fp16 per smem row (8-elem pad -> conflict-free ldsm)
#define TILE_E (128 * PITCH)            // 9216 fp16 per split tile
#define BUF_E  (4 * TILE_E)             // A(2) + B(2) per buffer
#define NCHUNK (CCH / BK)               // 8

__global__ __launch_bounds__(256, 1)
void conv_mma() {
    extern __shared__ __half sm[];

    const int tid = threadIdx.x;
    const int lane = tid & 31, warp = tid >> 5;
    const int wm = warp >> 2, wn = warp & 3;         // 2 x 4 warp grid, tile 64(m) x 32(n)
    const int which = blockIdx.z >> 3, b = blockIdx.z & 7;
    const int m0 = blockIdx.y * 128, p0 = blockIdx.x * 128;

    const __half* xs[2] = {g_x0[which], g_x1[which]};
    const __half* wsp[2] = {g_w0[which], g_w1[which]};
    float* F = which ? g_f_sar : g_f_opt;

    const uint32_t smA = smem_u32(sm);

    float acc[4][4][4];
#pragma unroll
    for (int i = 0; i < 4; i++)
#pragma unroll
        for (int j = 0; j < 4; j++)
#pragma unroll
            for (int k = 0; k < 4; k++) acc[i][j][k] = 0.f;

    // ---- async tile loader: 2048 cp.async x 16B per side ----
    auto load_chunk = [&](int c) {
        const int kc = c * BK;
        const int bi = c & 1;
        const uint32_t dstA = smA + bi * (BUF_E * 2);
        const uint32_t dstB = dstA + 2 * TILE_E * 2;
#pragma unroll
        for (int r = 0; r < 8; r++) {
            int i = tid + r * 256;                   // [0,2048)
            int s = i >> 10, rem = i & 1023, row = rem >> 3, seg = rem & 7;
            cp16(dstA + (s * TILE_E + row * PITCH + seg * 8) * 2,
                 wsp[s] + (size_t)(m0 + row) * CCH + kc + seg * 8);
        }
#pragma unroll
        for (int r = 0; r < 8; r++) {
            int i = tid + r * 256;
            int s = i >> 10, rem = i & 1023, row = rem >> 3, seg = rem & 7;
            cp16(dstB + (s * TILE_E + row * PITCH + seg * 8) * 2,
                 xs[s] + ((size_t)(b * PIX + p0 + row)) * CCH + kc + seg * 8);
        }
        CP_COMMIT();
    };

    load_chunk(0);

    const int sa_idx[3] = {0, 0, 1};
    const int sb_idx[3] = {0, 1, 0};

    for (int c = 0; c < NCHUNK; c++) {
        if (c + 1 < NCHUNK) { load_chunk(c + 1); CP_WAIT(1); }
        else                { CP_WAIT(0); }
        __syncthreads();

        const int bi = c & 1;
        const uint32_t bA = smA + bi * (BUF_E * 2);
        const uint32_t bB = bA + 2 * TILE_E * 2;

#pragma unroll
        for (int ks = 0; ks < 4; ks++) {
            uint32_t Af[2][4][4], Bf[2][4][2];
#pragma unroll
            for (int s = 0; s < 2; s++)
#pragma unroll
                for (int mi = 0; mi < 4; mi++) {
                    int row = wm * 64 + mi * 16 + (lane & 15);
                    int col = ks * 16 + ((lane >> 4) << 3);
                    ldsm4(Af[s][mi][0], Af[s][mi][1], Af[s][mi][2], Af[s][mi][3],
                          bA + (s * TILE_E + row * PITCH + col) * 2);
                }
#pragma unroll
            for (int s = 0; s < 2; s++)
#pragma unroll
                for (int ni = 0; ni < 2; ni++) {
                    int row = wn * 32 + ni * 16 + ((lane >> 4) << 3) + (lane & 7);
                    int col = ks * 16 + (((lane >> 3) & 1) << 3);
                    uint32_t r0, r1, r2, r3;
                    ldsm4(r0, r1, r2, r3, bB + (s * TILE_E + row * PITCH + col) * 2);
                    Bf[s][2 * ni][0] = r0; Bf[s][2 * ni][1] = r1;
                    Bf[s][2 * ni + 1][0] = r2; Bf[s][2 * ni + 1][1] = r3;
                }
#pragma unroll
            for (int pr = 0; pr < 3; pr++) {
                const int sa = sa_idx[pr], sb = sb_idx[pr];
#pragma unroll
                for (int mi = 0; mi < 4; mi++)
#pragma unroll
                    for (int nf = 0; nf < 4; nf++)
                        mma16816(acc[mi][nf], Af[sa][mi], Bf[sb][nf]);
            }
        }
        __syncthreads();
    }

    // ---- writeback
#pragma unroll
    for (int mi = 0; mi < 4; mi++) {
#pragma unroll
        for (int nf = 0; nf < 4; nf++) {
            int m = m0 + wm * 64 + mi * 16 + (lane >> 2);
            int n = p0 + wn * 32 + nf * 8 + (lane & 3) * 2;
            float* d0 = F + ((size_t)(b * CCH + m)) * PIX + n;
            *(float2*)d0 = make_float2(acc[mi][nf][0], acc[mi][nf][1]);
            *(float2*)(d0 + 8 * PIX) = make_float2(acc[mi][nf][2], acc[mi][nf][3]);
        }
    }
}

// ---------------- Kernel D: Gram matrices (both inputs in one launch) ----------------
__global__ __launch_bounds__(256)
void gram() {
    __shared__ float T[64 * 64];
    const int which = blockIdx.x >> 12;          // [0,8192): 4096 per input
    const int bc = blockIdx.x & 4095;
    const float* F = which ? g_f_sar : g_f_opt;
    float*       S = which ? g_S_sar : g_S_opt;
    const int tid = threadIdx.x;
    const float* src = F + (size_t)bc * PIX;

#pragma unroll
    for (int r = 0; r < 4; r++) {
        int s = tid + r * 256;
        *(float4*)&T[s * 4] = *(const float4*)(src + s * 4);
    }
    __syncthreads();

    const int tx = tid & 15, ty = tid >> 4;
    const int i0 = ty * 4, j0 = tx * 4;
    unsigned long long acc[4][2];
#pragma unroll
    for (int i = 0; i < 4; i++) { acc[i][0] = 0ull; acc[i][1] = 0ull; }

#pragma unroll 4
    for (int h = 0; h < 64; h++) {
        float4 a = *(const float4*)&T[h * 64 + i0];
        ulonglong2 bv = *(const ulonglong2*)&T[h * 64 + j0];
        float av[4] = {a.x, a.y, a.z, a.w};
#pragma unroll
        for (int i = 0; i < 4; i++) {
            unsigned long long ad = pack_dup(av[i]);
            ffma2(acc[i][0], ad, bv.x);
            ffma2(acc[i][1], ad, bv.y);
        }
    }
    float* dst = S + (size_t)bc * PIX;
#pragma unroll
    for (int i = 0; i < 4; i++) {
        float2 l0 = u2f(acc[i][0]), l1 = u2f(acc[i][1]);
        *(float4*)(dst + (i0 + i) * 64 + j0) = make_float4(l0.x, l0.y, l1.x, l1.y);
    }
}

// ---------------- Kernel E: channel softmax + combine ----------------
__global__ __launch_bounds__(128)
void smax_combine(float* __restrict__ out) {
    const int q = blockIdx.x * blockDim.x + threadIdx.x;
    const int b = q >> 12;
    const int p = q & (PIX - 1);
    const size_t bs = (size_t)b * CCH * PIX + p;
    const float* so = g_S_opt + bs;
    const float* ss = g_S_sar + bs;

    float mo = -3.0e38f, sumo = 0.f, ms = -3.0e38f, sums = 0.f;
#pragma unroll 8
    for (int c = 0; c < CCH; c++) {
        float v = so[(size_t)c * PIX];
        float w = ss[(size_t)c * PIX];
        float mo2 = fmaxf(mo, v);
        sumo = sumo * __expf(mo - mo2) + __expf(v - mo2); mo = mo2;
        float ms2 = fmaxf(ms, w);
        sums = sums * __expf(ms - ms2) + __expf(w - ms2); ms = ms2;
    }
    const float io = 1.0f / sumo, is = 1.0f / sums;
    const float* fo = g_f_opt + bs;
    const float* fs = g_f_sar + bs;
    float* o = out + bs;
#pragma unroll 8
    for (int c = 0; c < CCH; c++) {
        size_t off = (size_t)c * PIX;
        float had = (__expf(so[off] - mo) * io) * (__expf(ss[off] - ms) * is);
        o[off] = fo[off] * fs[off] * had * had;
    }
}

// ---------------- launch ----------------
extern "C" void kernel_launch(void* const* d_in, const int* in_sizes, int n_in,
                              void* d_out, int out_size) {
    const float* opt = (const float*)d_in[0];
    const float* sar = (const float*)d_in[1];
    const float* Wo  = (const float*)d_in[2];
    const float* Ws  = (const float*)d_in[3];
    float* out = (float*)d_out;

    static const int SMEM_CONV = 2 * BUF_E * 2;      // 147456 B
    cudaFuncSetAttribute(conv_mma, cudaFuncAttributeMaxDynamicSharedMemorySize, SMEM_CONV);

    dim3 gs(64, 8, 2 * BATCH);
    split_x<<<gs, 256>>>(opt, sar);
    split_w<<<dim3(CCH * CCH / 1024, 2), 256>>>(Wo, Ws);

    dim3 gc(PIX / 128, CCH / 128, 2 * BATCH);        // (32, 4, 16)
    conv_mma<<<gc, 256, SMEM_CONV>>>();

    gram<<<2 * BATCH * CCH, 256>>>();

    smax_combine<<<(BATCH * PIX) / 128, 128>>>(out);
}

// round 8
// speedup vs baseline: 1.7489x; 1.0809x over previous
#include <cuda_runtime.h>
#include <cuda_fp16.h>
#include <cstdint>

#define BATCH 8
#define CCH   512
#define PIX   4096
#define TOT   (BATCH*CCH*PIX)      // 16,777,216

// ---------------- scratch ----------------
__device__ float g_f_opt[TOT];
__device__ float g_f_sar[TOT];
__device__ float g_S_opt[TOT];
__device__ float g_S_sar[TOT];
__device__ float4 g_stats[2][BATCH*PIX];   // [c-half][pixel]: {mo,sumo,ms,sums}

__device__ __half g_x0[2][TOT];
__device__ __half g_x1[2][TOT];
__device__ __half g_w0[2][CCH*CCH];
__device__ __half g_w1[2][CCH*CCH];

// ---------------- helpers ----------------
__device__ __forceinline__ uint32_t smem_u32(const void* p) {
    uint32_t a;
    asm("{ .reg .u64 t; cvta.to.shared.u64 t, %1; cvt.u32.u64 %0, t; }" : "=r"(a) : "l"(p));
    return a;
}
__device__ __forceinline__ void cp16(uint32_t dst, const void* src) {
    asm volatile("cp.async.cg.shared.global [%0], [%1], 16;" :: "r"(dst), "l"(src));
}
#define CP_COMMIT() asm volatile("cp.async.commit_group;" ::: "memory")
#define CP_WAIT(n)  asm volatile("cp.async.wait_group %0;" :: "n"(n) : "memory")

__device__ __forceinline__ void ldsm4(uint32_t& r0, uint32_t& r1, uint32_t& r2, uint32_t& r3,
                                      uint32_t addr) {
    asm volatile("ldmatrix.sync.aligned.m8n8.x4.shared.b16 {%0,%1,%2,%3}, [%4];"
                 : "=r"(r0), "=r"(r1), "=r"(r2), "=r"(r3) : "r"(addr));
}
__device__ __forceinline__ void mma16816(float* c, const uint32_t* a, const uint32_t* b) {
    asm volatile("mma.sync.aligned.m16n8k16.row.col.f32.f16.f16.f32 "
                 "{%0,%1,%2,%3}, {%4,%5,%6,%7}, {%8,%9}, {%0,%1,%2,%3};"
                 : "+f"(c[0]), "+f"(c[1]), "+f"(c[2]), "+f"(c[3])
                 : "r"(a[0]), "r"(a[1]), "r"(a[2]), "r"(a[3]), "r"(b[0]), "r"(b[1]));
}

// ---------------- Kernel: split + transpose X ----------------
__global__ __launch_bounds__(256)
void split_x(const float* __restrict__ opt, const float* __restrict__ sar) {
    __shared__ float tile[64 * 68];
    const int which = blockIdx.z >> 3, b = blockIdx.z & 7;
    const int c0 = blockIdx.y * 64, p0 = blockIdx.x * 64;
    const int tid = threadIdx.x;
    const float* x = which ? sar : opt;

    const float* src = x + ((size_t)(b * CCH + c0)) * PIX + p0;
    const int cl = tid >> 4, pl4 = (tid & 15) * 4;
#pragma unroll
    for (int it = 0; it < 4; it++) {
        float4 v = *(const float4*)(src + (size_t)(cl + it * 16) * PIX + pl4);
        *(float4*)&tile[(cl + it * 16) * 68 + pl4] = v;
    }
    __syncthreads();

    const int pl = tid >> 2, q = (tid & 3) * 16;
    __half o0[16], o1[16];
#pragma unroll
    for (int j = 0; j < 16; j++) {
        float a = tile[(q + j) * 68 + pl];
        __half h = __float2half_rn(a);
        o0[j] = h;
        o1[j] = __float2half_rn(a - __half2float(h));
    }
    size_t off = ((size_t)(b * PIX + p0 + pl)) * CCH + c0 + q;
    ((uint4*)&g_x0[which][off])[0] = ((uint4*)o0)[0];
    ((uint4*)&g_x0[which][off])[1] = ((uint4*)o0)[1];
    ((uint4*)&g_x1[which][off])[0] = ((uint4*)o1)[0];
    ((uint4*)&g_x1[which][off])[1] = ((uint4*)o1)[1];
}

// ---------------- Kernel: split W ----------------
__global__ __launch_bounds__(256)
void split_w(const float* __restrict__ Wo, const float* __restrict__ Ws) {
    const int which = blockIdx.y;
    const float* w = which ? Ws : Wo;
    int i = (blockIdx.x * 256 + threadIdx.x) * 4;
    float4 v = *(const float4*)(w + i);
    float av[4] = {v.x, v.y, v.z, v.w};
    __half o0[4], o1[4];
#pragma unroll
    for (int j = 0; j < 4; j++) {
        __half h = __float2half_rn(av[j]);
        o0[j] = h;
        o1[j] = __float2half_rn(av[j] - __half2float(h));
    }
    *(uint2*)&g_w0[which][i] = *(uint2*)o0;
    *(uint2*)&g_w1[which][i] = *(uint2*)o1;
}

// ---------------- Kernel: conv via mma.sync, fp16 2-split ----------------
#define BK     64
#define PITCH  72
#define TILE_E (128 * PITCH)
#define BUF_E  (4 * TILE_E)
#define NCHUNK (CCH / BK)

__global__ __launch_bounds__(256, 1)
void conv_mma(int which) {
    extern __shared__ __half sm[];

    const int tid = threadIdx.x;
    const int lane = tid & 31, warp = tid >> 5;
    const int wm = warp >> 2, wn = warp & 3;
    const int b = blockIdx.z;
    const int m0 = blockIdx.y * 128, p0 = blockIdx.x * 128;

    const __half* xs[2] = {g_x0[which], g_x1[which]};
    const __half* wsp[2] = {g_w0[which], g_w1[which]};
    float* F = which ? g_f_sar : g_f_opt;

    const uint32_t smA = smem_u32(sm);

    float acc[4][4][4];
#pragma unroll
    for (int i = 0; i < 4; i++)
#pragma unroll
        for (int j = 0; j < 4; j++)
#pragma unroll
            for (int k = 0; k < 4; k++) acc[i][j][k] = 0.f;

    auto load_chunk = [&](int c) {
        const int kc = c * BK;
        const int bi = c & 1;
        const uint32_t dstA = smA + bi * (BUF_E * 2);
        const uint32_t dstB = dstA + 2 * TILE_E * 2;
#pragma unroll
        for (int r = 0; r < 8; r++) {
            int i = tid + r * 256;
            int s = i >> 10, rem = i & 1023, row = rem >> 3, seg = rem & 7;
            cp16(dstA + (s * TILE_E + row * PITCH + seg * 8) * 2,
                 wsp[s] + (size_t)(m0 + row) * CCH + kc + seg * 8);
        }
#pragma unroll
        for (int r = 0; r < 8; r++) {
            int i = tid + r * 256;
            int s = i >> 10, rem = i & 1023, row = rem >> 3, seg = rem & 7;
            cp16(dstB + (s * TILE_E + row * PITCH + seg * 8) * 2,
                 xs[s] + ((size_t)(b * PIX + p0 + row)) * CCH + kc + seg * 8);
        }
        CP_COMMIT();
    };

    load_chunk(0);

    const int sa_idx[3] = {0, 0, 1};
    const int sb_idx[3] = {0, 1, 0};

    for (int c = 0; c < NCHUNK; c++) {
        if (c + 1 < NCHUNK) { load_chunk(c + 1); CP_WAIT(1); }
        else                { CP_WAIT(0); }
        __syncthreads();

        const int bi = c & 1;
        const uint32_t bA = smA + bi * (BUF_E * 2);
        const uint32_t bB = bA + 2 * TILE_E * 2;

#pragma unroll
        for (int ks = 0; ks < 4; ks++) {
            uint32_t Af[2][4][4], Bf[2][4][2];
#pragma unroll
            for (int s = 0; s < 2; s++)
#pragma unroll
                for (int mi = 0; mi < 4; mi++) {
                    int row = wm * 64 + mi * 16 + (lane & 15);
                    int col = ks * 16 + ((lane >> 4) << 3);
                    ldsm4(Af[s][mi][0], Af[s][mi][1], Af[s][mi][2], Af[s][mi][3],
                          bA + (s * TILE_E + row * PITCH + col) * 2);
                }
#pragma unroll
            for (int s = 0; s < 2; s++)
#pragma unroll
                for (int ni = 0; ni < 2; ni++) {
                    int row = wn * 32 + ni * 16 + ((lane >> 4) << 3) + (lane & 7);
                    int col = ks * 16 + (((lane >> 3) & 1) << 3);
                    uint32_t r0, r1, r2, r3;
                    ldsm4(r0, r1, r2, r3, bB + (s * TILE_E + row * PITCH + col) * 2);
                    Bf[s][2 * ni][0] = r0; Bf[s][2 * ni][1] = r1;
                    Bf[s][2 * ni + 1][0] = r2; Bf[s][2 * ni + 1][1] = r3;
                }
#pragma unroll
            for (int pr = 0; pr < 3; pr++) {
                const int sa = sa_idx[pr], sb = sb_idx[pr];
#pragma unroll
                for (int mi = 0; mi < 4; mi++)
#pragma unroll
                    for (int nf = 0; nf < 4; nf++)
                        mma16816(acc[mi][nf], Af[sa][mi], Bf[sb][nf]);
            }
        }
        __syncthreads();
    }

#pragma unroll
    for (int mi = 0; mi < 4; mi++) {
#pragma unroll
        for (int nf = 0; nf < 4; nf++) {
            int m = m0 + wm * 64 + mi * 16 + (lane >> 2);
            int n = p0 + wn * 32 + nf * 8 + (lane & 3) * 2;
            float* d0 = F + ((size_t)(b * CCH + m)) * PIX + n;
            *(float2*)d0 = make_float2(acc[mi][nf][0], acc[mi][nf][1]);
            *(float2*)(d0 + 8 * PIX) = make_float2(acc[mi][nf][2], acc[mi][nf][3]);
        }
    }
}

// ---------------- Kernel: Gram via mma.sync, fp16 2-split ----------------
// S[bc][i][j] = sum_h F[h][i] F[h][j].  Both A and B frags read rows of FT=[i][h].
#define GP 72
__global__ __launch_bounds__(256)
void gram_mma() {
    __shared__ float  Ts[64 * 68];
    __shared__ __half FT0[64 * GP];
    __shared__ __half FT1[64 * GP];

    const int which = blockIdx.x >> 12;
    const int bc = blockIdx.x & 4095;
    const float* F = which ? g_f_sar : g_f_opt;
    float*       S = which ? g_S_sar : g_S_opt;
    const int tid = threadIdx.x;
    const int lane = tid & 31, warp = tid >> 5;
    const float* src = F + (size_t)bc * PIX;

    // stage fp32 F [h][i]
    {
        const int h = tid >> 4, i4 = (tid & 15) * 4;
#pragma unroll
        for (int it = 0; it < 4; it++) {
            float4 v = *(const float4*)(src + (h + it * 16) * 64 + i4);
            *(float4*)&Ts[(h + it * 16) * 68 + i4] = v;
        }
    }
    __syncthreads();

    // transpose + fp16 2-split -> FT0/FT1 [i][h]
    {
        const int i = tid >> 2, hq = (tid & 3) * 16;
        __half o0[16], o1[16];
#pragma unroll
        for (int j = 0; j < 16; j++) {
            float a = Ts[(hq + j) * 68 + i];
            __half h0 = __float2half_rn(a);
            o0[j] = h0;
            o1[j] = __float2half_rn(a - __half2float(h0));
        }
        *(uint4*)&FT0[i * GP + hq]     = ((uint4*)o0)[0];
        *(uint4*)&FT0[i * GP + hq + 8] = ((uint4*)o0)[1];
        *(uint4*)&FT1[i * GP + hq]     = ((uint4*)o1)[0];
        *(uint4*)&FT1[i * GP + hq + 8] = ((uint4*)o1)[1];
    }
    __syncthreads();

    // 8 warps: warp -> m-tile (warp>>1)*16, n-half (warp&1)*32
    const int m0 = (warp >> 1) * 16, n0 = (warp & 1) * 32;
    const uint32_t ft[2] = {smem_u32(FT0), smem_u32(FT1)};

    float acc[4][4];
#pragma unroll
    for (int i = 0; i < 4; i++)
#pragma unroll
        for (int j = 0; j < 4; j++) acc[i][j] = 0.f;

    const int sa_idx[3] = {0, 0, 1};
    const int sb_idx[3] = {0, 1, 0};

#pragma unroll
    for (int ks = 0; ks < 4; ks++) {
        uint32_t Af[2][4], Bf[2][4][2];
#pragma unroll
        for (int s = 0; s < 2; s++) {
            int row = m0 + (lane & 15);
            int col = ks * 16 + ((lane >> 4) << 3);
            ldsm4(Af[s][0], Af[s][1], Af[s][2], Af[s][3],
                  ft[s] + (row * GP + col) * 2);
        }
#pragma unroll
        for (int s = 0; s < 2; s++)
#pragma unroll
            for (int ni = 0; ni < 2; ni++) {
                int row = n0 + ni * 16 + ((lane >> 4) << 3) + (lane & 7);
                int col = ks * 16 + (((lane >> 3) & 1) << 3);
                uint32_t r0, r1, r2, r3;
                ldsm4(r0, r1, r2, r3, ft[s] + (row * GP + col) * 2);
                Bf[s][2 * ni][0] = r0; Bf[s][2 * ni][1] = r1;
                Bf[s][2 * ni + 1][0] = r2; Bf[s][2 * ni + 1][1] = r3;
            }
#pragma unroll
        for (int pr = 0; pr < 3; pr++)
#pragma unroll
            for (int nf = 0; nf < 4; nf++)
                mma16816(acc[nf], Af[sa_idx[pr]], Bf[sb_idx[pr]][nf]);
    }

    float* dst = S + (size_t)bc * PIX;
#pragma unroll
    for (int nf = 0; nf < 4; nf++) {
        int m = m0 + (lane >> 2);
        int n = n0 + nf * 8 + (lane & 3) * 2;
        *(float2*)(dst + m * 64 + n)       = make_float2(acc[nf][0], acc[nf][1]);
        *(float2*)(dst + (m + 8) * 64 + n) = make_float2(acc[nf][2], acc[nf][3]);
    }
}

// ---------------- Kernel: softmax stats (phase 1, c split in half) ----------------
__global__ __launch_bounds__(256)
void smax_stats() {
    const int g = blockIdx.x * 256 + threadIdx.x;       // [0, 65536)
    const int s = g >> 15;                              // c half
    const int q = g & 32767;                            // pixel
    const int b = q >> 12, p = q & (PIX - 1);
    const size_t base = (size_t)b * CCH * PIX + (size_t)s * 256 * PIX + p;
    const float* so = g_S_opt + base;
    const float* ss = g_S_sar + base;

    float mo = -3.0e38f, sumo = 0.f, ms = -3.0e38f, sums = 0.f;
#pragma unroll 8
    for (int cc = 0; cc < 256; cc++) {
        float v = so[(size_t)cc * PIX];
        float w = ss[(size_t)cc * PIX];
        float mo2 = fmaxf(mo, v);
        sumo = sumo * __expf(mo - mo2) + __expf(v - mo2); mo = mo2;
        float ms2 = fmaxf(ms, w);
        sums = sums * __expf(ms - ms2) + __expf(w - ms2); ms = ms2;
    }
    g_stats[s][q] = make_float4(mo, sumo, ms, sums);
}

// ---------------- Kernel: combine (phase 2) ----------------
__global__ __launch_bounds__(256)
void smax_combine(float* __restrict__ out) {
    const int g = blockIdx.x * 256 + threadIdx.x;
    const int s = g >> 15;
    const int q = g & 32767;
    const int b = q >> 12, p = q & (PIX - 1);

    float4 s0 = g_stats[0][q], s1 = g_stats[1][q];
    const float mo = fmaxf(s0.x, s1.x);
    const float io = 1.0f / (s0.y * __expf(s0.x - mo) + s1.y * __expf(s1.x - mo));
    const float ms = fmaxf(s0.z, s1.z);
    const float is = 1.0f / (s0.w * __expf(s0.z - ms) + s1.w * __expf(s1.z - ms));

    const size_t base = (size_t)b * CCH * PIX + (size_t)s * 256 * PIX + p;
    const float* so = g_S_opt + base;
    const float* ss = g_S_sar + base;
    const float* fo = g_f_opt + base;
    const float* fs = g_f_sar + base;
    float* o = out + base;

#pragma unroll 8
    for (int cc = 0; cc < 256; cc++) {
        size_t off = (size_t)cc * PIX;
        float had = (__expf(so[off] - mo) * io) * (__expf(ss[off] - ms) * is);
        o[off] = fo[off] * fs[off] * had * had;
    }
}

// ---------------- launch ----------------
extern "C" void kernel_launch(void* const* d_in, const int* in_sizes, int n_in,
                              void* d_out, int out_size) {
    const float* opt = (const float*)d_in[0];
    const float* sar = (const float*)d_in[1];
    const float* Wo  = (const float*)d_in[2];
    const float* Ws  = (const float*)d_in[3];
    float* out = (float*)d_out;

    static const int SMEM_CONV = 2 * BUF_E * 2;      // 147456 B
    cudaFuncSetAttribute(conv_mma, cudaFuncAttributeMaxDynamicSharedMemorySize, SMEM_CONV);

    dim3 gs(64, 8, 2 * BATCH);
    split_x<<<gs, 256>>>(opt, sar);                          // idx 0
    split_w<<<dim3(CCH * CCH / 1024, 2), 256>>>(Wo, Ws);     // idx 1

    dim3 gc(PIX / 128, CCH / 128, BATCH);
    conv_mma<<<gc, 256, SMEM_CONV>>>(0);                     // idx 2
    conv_mma<<<gc, 256, SMEM_CONV>>>(1);                     // idx 3  <- profiled

    gram_mma<<<2 * BATCH * CCH, 256>>>();                    // idx 4

    smax_stats<<<(2 * BATCH * PIX) / 256, 256>>>();          // idx 5
    smax_combine<<<(2 * BATCH * PIX) / 256, 256>>>(out);     // idx 6
}